// round 6
// baseline (speedup 1.0000x reference)
#include <cuda_runtime.h>
#include <math.h>

#define BB 4
#define NN 512
#define FF 256
#define EE 64
#define TILE_I 16
#define LRELU_ALPHA 0.2f
#define NEG_INF_V -1e30f

#define GEMM_CTAS 256   // 64 m-tiles x 4 n-tiles

// scratch (no allocations allowed)
__device__ float g_h[BB*NN*FF];        // 2 MB
__device__ float g_sip[4*BB*NN];       // per-n-tile partial s_i
__device__ float g_sjp[4*BB*NN];       // per-n-tile partial s_j
__device__ float g_w1a3[EE];
__device__ int   g_flag;               // w1a3-ready flag (values run-invariant -> sticky OK)
__device__ float g_sc[BB*NN*NN];       // 4 MB raw edge scores

// ---- f32x2 packed helpers (Blackwell FFMA2) ----
__device__ __forceinline__ unsigned long long ffma2(unsigned long long a,
                                                    unsigned long long b,
                                                    unsigned long long c) {
    unsigned long long d;
    asm("fma.rn.f32x2 %0, %1, %2, %3;" : "=l"(d) : "l"(a), "l"(b), "l"(c));
    return d;
}
__device__ __forceinline__ unsigned long long pack2(float lo, float hi) {
    unsigned long long d;
    asm("mov.b64 %0, {%1, %2};" : "=l"(d) : "f"(lo), "f"(hi));
    return d;
}
__device__ __forceinline__ void unpack2(unsigned long long v, float& lo, float& hi) {
    asm("mov.b64 {%0, %1}, %2;" : "=f"(lo), "=f"(hi) : "l"(v));
}

// ================= Kernel 1: MEGA =================
// bid 0          : w1a3 = W1@a3 -> flag release, then its GEMM tile
// bid < GEMM_CTAS: h = x@W 32x64 tile; epilogue writes si/sj partial dots
// bid >= GEMM_CTAS: score row bi (268MB DRAM stream), per-thread-j FFMA2 dots
__global__ __launch_bounds__(256) void mega_kernel(const float* __restrict__ X,
                                                   const float* __restrict__ Wm,
                                                   const float* __restrict__ edge,
                                                   const float* __restrict__ W1,
                                                   const float* __restrict__ a) {
    __shared__ __align__(16) float As[16][33];   // gemm path
    __shared__ __align__(16) float Bs[16][68];
    __shared__ __align__(16) float s_w[EE];      // score path

    const int tid = threadIdx.x;

    if (blockIdx.x < GEMM_CTAS) {
        // ---------------- w1a3 prologue (bid 0 only) ----------------
        if (blockIdx.x == 0) {
            const int e = tid >> 2;
            const int q = tid & 3;
            const float* wrow = W1 + (size_t)e*FF + q*64;
            const float* a3   = a + 2*FF + q*64;
            float p = 0.f;
            #pragma unroll
            for (int iq = 0; iq < 16; iq++) {
                float4 wv4 = *(const float4*)&wrow[iq*4];
                float4 av4 = *(const float4*)&a3[iq*4];
                p += wv4.x*av4.x + wv4.y*av4.y + wv4.z*av4.z + wv4.w*av4.w;
            }
            p += __shfl_xor_sync(0xffffffffu, p, 1);
            p += __shfl_xor_sync(0xffffffffu, p, 2);
            if (q == 0) g_w1a3[e] = p;
            __syncthreads();
            if (tid == 0) {
                __threadfence();
                atomicExch(&g_flag, 1);
            }
        }

        // ---------------- GEMM path ----------------
        const int bmi = blockIdx.x & 63;
        const int bni = blockIdx.x >> 6;
        const int bm = bmi * 32;
        const int bn = bni * 64;
        const int tx = tid & 15;
        const int ty = tid >> 4;
        const int ar = tid >> 3;
        const int ac = (tid & 7) * 2;
        const int br = tid >> 4;
        const int bc = (tid & 15) * 4;

        unsigned long long acc00 = 0, acc01 = 0, acc10 = 0, acc11 = 0;
        for (int k0 = 0; k0 < FF; k0 += 16) {
            float2 xa = *(const float2*)&X[(size_t)(bm + ar)*FF + k0 + ac];
            As[ac][ar] = xa.x; As[ac+1][ar] = xa.y;
            *(float4*)&Bs[br][bc] = *(const float4*)&Wm[(size_t)(k0 + br)*FF + bn + bc];
            __syncthreads();
            #pragma unroll
            for (int k = 0; k < 16; k++) {
                float a0 = As[k][ty*2+0];
                float a1 = As[k][ty*2+1];
                unsigned long long a0d = pack2(a0, a0);
                unsigned long long a1d = pack2(a1, a1);
                ulonglong2 bq = *(const ulonglong2*)&Bs[k][tx*4];
                acc00 = ffma2(a0d, bq.x, acc00);
                acc01 = ffma2(a0d, bq.y, acc01);
                acc10 = ffma2(a1d, bq.x, acc10);
                acc11 = ffma2(a1d, bq.y, acc11);
            }
            __syncthreads();
        }
        float c00, c01, c02, c03, c10, c11, c12, c13;
        unpack2(acc00, c00, c01); unpack2(acc01, c02, c03);
        unpack2(acc10, c10, c11); unpack2(acc11, c12, c13);
        *(float4*)&g_h[(size_t)(bm + ty*2 + 0)*FF + bn + tx*4] = make_float4(c00, c01, c02, c03);
        *(float4*)&g_h[(size_t)(bm + ty*2 + 1)*FF + bn + tx*4] = make_float4(c10, c11, c12, c13);

        // epilogue: partial s_i/s_j over this n-tile
        const float4 a1v = *(const float4*)&a[bn + tx*4];
        const float4 a2v = *(const float4*)&a[FF + bn + tx*4];
        float pi0 = c00*a1v.x + c01*a1v.y + c02*a1v.z + c03*a1v.w;
        float pi1 = c10*a1v.x + c11*a1v.y + c12*a1v.z + c13*a1v.w;
        float pj0 = c00*a2v.x + c01*a2v.y + c02*a2v.z + c03*a2v.w;
        float pj1 = c10*a2v.x + c11*a2v.y + c12*a2v.z + c13*a2v.w;
        #pragma unroll
        for (int o = 8; o > 0; o >>= 1) {
            pi0 += __shfl_xor_sync(0xffffffffu, pi0, o);
            pi1 += __shfl_xor_sync(0xffffffffu, pi1, o);
            pj0 += __shfl_xor_sync(0xffffffffu, pj0, o);
            pj1 += __shfl_xor_sync(0xffffffffu, pj1, o);
        }
        if (tx == 0) {
            g_sip[bni*(BB*NN) + bm + ty*2 + 0] = pi0;
            g_sip[bni*(BB*NN) + bm + ty*2 + 1] = pi1;
            g_sjp[bni*(BB*NN) + bm + ty*2 + 0] = pj0;
            g_sjp[bni*(BB*NN) + bm + ty*2 + 1] = pj1;
        }
    } else {
        // ---------------- SCORE path (268 MB edge stream) ----------------
        const int bi = blockIdx.x - GEMM_CTAS;          // b*NN + i

        // wait for w1a3 (bid 0 is resident in wave 1 -> guaranteed progress)
        if (tid < 32) {
            while (atomicAdd(&g_flag, 0) == 0) __nanosleep(100);
        }
        __syncthreads();
        if (tid == 0) __threadfence();
        if (tid < EE) s_w[tid] = g_w1a3[tid];
        __syncthreads();

        const ulonglong2* wv = (const ulonglong2*)s_w;   // 16 x 16B
        const float* ebase = edge + (size_t)bi * NN * EE;

        #pragma unroll
        for (int pass = 0; pass < 2; pass++) {
            const int j = pass*256 + tid;
            const ulonglong2* ej = (const ulonglong2*)(ebase + (size_t)j * EE);
            unsigned long long accA = 0ull, accB = 0ull;
            #pragma unroll
            for (int u = 0; u < 16; u += 4) {
                ulonglong2 e0 = ej[u+0];
                ulonglong2 e1 = ej[u+1];
                ulonglong2 e2 = ej[u+2];
                ulonglong2 e3 = ej[u+3];
                ulonglong2 w0 = wv[u+0];
                ulonglong2 w1 = wv[u+1];
                ulonglong2 w2 = wv[u+2];
                ulonglong2 w3 = wv[u+3];
                accA = ffma2(e0.x, w0.x, accA); accB = ffma2(e0.y, w0.y, accB);
                accA = ffma2(e1.x, w1.x, accA); accB = ffma2(e1.y, w1.y, accB);
                accA = ffma2(e2.x, w2.x, accA); accB = ffma2(e2.y, w2.y, accB);
                accA = ffma2(e3.x, w3.x, accA); accB = ffma2(e3.y, w3.y, accB);
            }
            float a0, a1, b0, b1;
            unpack2(accA, a0, a1);
            unpack2(accB, b0, b1);
            g_sc[(size_t)bi*NN + j] = (a0 + a1) + (b0 + b1);
        }
    }
}

// ================= Kernel 2: softmax + attn@h + elu; TILE_I=16, 2 f/thread ======
// grid = 128 (b x 32 tiles), block 512 = 4 j-quarters x 128 f-lanes.
__global__ __launch_bounds__(512) void softmax_av_kernel(const float* __restrict__ adj,
                                                         float* __restrict__ out) {
    __shared__ __align__(16) float2 sh_ap[TILE_I/2][NN];  // packed (2r,2r+1) attn, 32KB
    __shared__ float redm[TILE_I][16];
    __shared__ float reds[TILE_I][16];
    __shared__ float s_si[TILE_I];

    const int tid  = threadIdx.x;
    const int b    = blockIdx.x >> 5;
    const int i0   = (blockIdx.x & 31) * TILE_I;
    const int lane = tid & 31;
    const int wid  = tid >> 5;

    if (tid < TILE_I) {
        float s = 0.f;
        #pragma unroll
        for (int t = 0; t < 4; t++) s += g_sip[t*(BB*NN) + b*NN + i0 + tid];
        s_si[tid] = s;
    }
    float sj = 0.f;
    #pragma unroll
    for (int t = 0; t < 4; t++) sj += g_sjp[t*(BB*NN) + b*NN + tid];
    __syncthreads();

    // ---- masked lrelu scores for 16 rows, column j = tid ----
    float v[TILE_I];
    const float* scb  = g_sc + (size_t)(b*NN + i0)*NN;
    const float* adjb = adj  + (size_t)(b*NN + i0)*NN;
    #pragma unroll
    for (int r = 0; r < TILE_I; r++) {
        float e = s_si[r] + sj + scb[(size_t)r*NN + tid];
        e = (e >= 0.f) ? e : LRELU_ALPHA * e;
        v[r] = (adjb[(size_t)r*NN + tid] > 0.f) ? e : NEG_INF_V;
    }
    #pragma unroll
    for (int r = 0; r < TILE_I; r++) {
        float m = v[r];
        #pragma unroll
        for (int o = 16; o > 0; o >>= 1)
            m = fmaxf(m, __shfl_xor_sync(0xffffffffu, m, o));
        if (lane == 0) redm[r][wid] = m;
    }
    __syncthreads();
    #pragma unroll
    for (int r = 0; r < TILE_I; r++) {
        float bm = redm[r][0];
        #pragma unroll
        for (int wq = 1; wq < 16; wq++) bm = fmaxf(bm, redm[r][wq]);
        v[r] = __expf(v[r] - bm);
        float s = v[r];
        #pragma unroll
        for (int o = 16; o > 0; o >>= 1)
            s += __shfl_xor_sync(0xffffffffu, s, o);
        if (lane == 0) reds[r][wid] = s;
    }
    __syncthreads();
    #pragma unroll
    for (int rp = 0; rp < TILE_I/2; rp++) {
        float s0 = 0.f, s1 = 0.f;
        #pragma unroll
        for (int wq = 0; wq < 16; wq++) { s0 += reds[2*rp][wq]; s1 += reds[2*rp+1][wq]; }
        sh_ap[rp][tid] = make_float2(v[2*rp] / s0, v[2*rp+1] / s1);
    }
    __syncthreads();

    // ---- attn @ h: 4 j-quarters, 2 f per thread (fl, fl+128); row-pair FFMA2 ----
    const int jq = tid >> 7;             // 0..3
    const int fl = tid & 127;
    unsigned long long acc0[TILE_I/2] = {};   // f = fl
    unsigned long long acc1[TILE_I/2] = {};   // f = fl + 128
    const float* hb = g_h + (size_t)b*NN*FF;

    for (int jt = jq*128; jt < jq*128 + 128; jt += 4) {
        unsigned long long hd0[4], hd1[4];
        #pragma unroll
        for (int u = 0; u < 4; u++) {
            float h0 = hb[(size_t)(jt + u)*FF + fl];
            float h1 = hb[(size_t)(jt + u)*FF + fl + 128];
            hd0[u] = pack2(h0, h0);
            hd1[u] = pack2(h1, h1);
        }
        #pragma unroll
        for (int rp = 0; rp < TILE_I/2; rp++) {
            ulonglong2 q0 = *(const ulonglong2*)&sh_ap[rp][jt + 0];
            ulonglong2 q1 = *(const ulonglong2*)&sh_ap[rp][jt + 2];
            acc0[rp] = ffma2(q0.x, hd0[0], acc0[rp]);
            acc0[rp] = ffma2(q0.y, hd0[1], acc0[rp]);
            acc0[rp] = ffma2(q1.x, hd0[2], acc0[rp]);
            acc0[rp] = ffma2(q1.y, hd0[3], acc0[rp]);
            acc1[rp] = ffma2(q0.x, hd1[0], acc1[rp]);
            acc1[rp] = ffma2(q0.y, hd1[1], acc1[rp]);
            acc1[rp] = ffma2(q1.x, hd1[2], acc1[rp]);
            acc1[rp] = ffma2(q1.y, hd1[3], acc1[rp]);
        }
    }

    // ---- combine 4 quarters via 32KB sh_ap overlay, ELU, store ----
    // buf layout: [src(0..1)][rp(0..7)][fsel(0..1)][fl(0..127)]
    __syncthreads();
    float2* buf = (float2*)&sh_ap[0][0];   // 4096 float2 = 32KB
    if (jq >= 2) {
        #pragma unroll
        for (int rp = 0; rp < TILE_I/2; rp++) {
            float lo, hi;
            unpack2(acc0[rp], lo, hi);
            buf[(((jq-2)*8 + rp)*2 + 0)*128 + fl] = make_float2(lo, hi);
            unpack2(acc1[rp], lo, hi);
            buf[(((jq-2)*8 + rp)*2 + 1)*128 + fl] = make_float2(lo, hi);
        }
    }
    __syncthreads();
    if (jq < 2) {   // q0 += q2's partial; q1 += q3's partial
        #pragma unroll
        for (int rp = 0; rp < TILE_I/2; rp++) {
            float2 p0 = buf[((jq*8 + rp)*2 + 0)*128 + fl];
            float2 p1 = buf[((jq*8 + rp)*2 + 1)*128 + fl];
            float lo, hi;
            unpack2(acc0[rp], lo, hi);
            acc0[rp] = pack2(lo + p0.x, hi + p0.y);
            unpack2(acc1[rp], lo, hi);
            acc1[rp] = pack2(lo + p1.x, hi + p1.y);
        }
    }
    __syncthreads();
    if (jq == 1) {
        #pragma unroll
        for (int rp = 0; rp < TILE_I/2; rp++) {
            float lo, hi;
            unpack2(acc0[rp], lo, hi);
            buf[((rp)*2 + 0)*128 + fl] = make_float2(lo, hi);
            unpack2(acc1[rp], lo, hi);
            buf[((rp)*2 + 1)*128 + fl] = make_float2(lo, hi);
        }
    }
    __syncthreads();
    if (jq == 0) {
        #pragma unroll
        for (int rp = 0; rp < TILE_I/2; rp++) {
            float2 p0 = buf[((rp)*2 + 0)*128 + fl];
            float2 p1 = buf[((rp)*2 + 1)*128 + fl];
            float lo, hi;
            unpack2(acc0[rp], lo, hi);
            float v00 = lo + p0.x, v01 = hi + p0.y;
            unpack2(acc1[rp], lo, hi);
            float v10 = lo + p1.x, v11 = hi + p1.y;
            out[(size_t)(b*NN + i0 + 2*rp + 0)*FF + fl]       = (v00 > 0.f) ? v00 : expm1f(v00);
            out[(size_t)(b*NN + i0 + 2*rp + 1)*FF + fl]       = (v01 > 0.f) ? v01 : expm1f(v01);
            out[(size_t)(b*NN + i0 + 2*rp + 0)*FF + fl + 128] = (v10 > 0.f) ? v10 : expm1f(v10);
            out[(size_t)(b*NN + i0 + 2*rp + 1)*FF + fl + 128] = (v11 > 0.f) ? v11 : expm1f(v11);
        }
    }
}

// ================= launcher =================
extern "C" void kernel_launch(void* const* d_in, const int* in_sizes, int n_in,
                              void* d_out, int out_size) {
    const float* x    = (const float*)d_in[0];  // [4,512,256]
    const float* edge = (const float*)d_in[1];  // [4,512,512,64]
    const float* adj  = (const float*)d_in[2];  // [4,512,512]
    const float* W    = (const float*)d_in[3];  // [256,256]
    const float* W1   = (const float*)d_in[4];  // [64,256]
    const float* a    = (const float*)d_in[5];  // [768,1]
    float* out = (float*)d_out;                 // [4,512,256]

    mega_kernel<<<GEMM_CTAS + BB*NN, 256>>>(x, W, edge, W1, a);
    softmax_av_kernel<<<BB*NN/TILE_I, 512>>>(adj, out);
}

// round 7
// speedup vs baseline: 1.2863x; 1.2863x over previous
#include <cuda_runtime.h>
#include <math.h>

#define BB 4
#define NN 512
#define FF 256
#define EE 64
#define TILE_I 8
#define LRELU_ALPHA 0.2f
#define NEG_INF_V -1e30f

#define GEMM_CTAS 256   // 64 m-tiles x 4 n-tiles

// scratch (no allocations allowed)
__device__ float g_h[BB*NN*FF];        // 2 MB
__device__ float g_sip[4*BB*NN];       // per-n-tile partial s_i
__device__ float g_sjp[4*BB*NN];       // per-n-tile partial s_j
__device__ float g_w1a3[EE];
__device__ int   g_flag;               // w1a3-ready flag (values run-invariant -> sticky OK)
__device__ float g_sc[BB*NN*NN];       // 4 MB raw edge scores

// ---- f32x2 packed helpers (Blackwell FFMA2) ----
__device__ __forceinline__ unsigned long long ffma2(unsigned long long a,
                                                    unsigned long long b,
                                                    unsigned long long c) {
    unsigned long long d;
    asm("fma.rn.f32x2 %0, %1, %2, %3;" : "=l"(d) : "l"(a), "l"(b), "l"(c));
    return d;
}
__device__ __forceinline__ unsigned long long pack2(float lo, float hi) {
    unsigned long long d;
    asm("mov.b64 %0, {%1, %2};" : "=l"(d) : "f"(lo), "f"(hi));
    return d;
}
__device__ __forceinline__ void unpack2(unsigned long long v, float& lo, float& hi) {
    asm("mov.b64 {%0, %1}, %2;" : "=f"(lo), "=f"(hi) : "l"(v));
}

// ================= Kernel 1: MEGA =================
// bid 0          : w1a3 = W1@a3 -> flag release, then its GEMM tile
// bid < GEMM_CTAS: h = x@W 32x64 tile; epilogue writes si/sj partial dots
// bid >= GEMM_CTAS: score row bi (268MB DRAM stream), 16-lane-per-j coalesced
__global__ __launch_bounds__(256) void mega_kernel(const float* __restrict__ X,
                                                   const float* __restrict__ Wm,
                                                   const float* __restrict__ edge,
                                                   const float* __restrict__ W1,
                                                   const float* __restrict__ a) {
    __shared__ __align__(16) float As[16][33];   // gemm path
    __shared__ __align__(16) float Bs[16][68];
    __shared__ float s_w[EE];                    // score path
    __shared__ float s_sc[NN];

    const int tid = threadIdx.x;

    if (blockIdx.x < GEMM_CTAS) {
        // ---------------- w1a3 prologue (bid 0 only) ----------------
        if (blockIdx.x == 0) {
            const int e = tid >> 2;
            const int q = tid & 3;
            const float* wrow = W1 + (size_t)e*FF + q*64;
            const float* a3   = a + 2*FF + q*64;
            float p = 0.f;
            #pragma unroll
            for (int iq = 0; iq < 16; iq++) {
                float4 wv4 = *(const float4*)&wrow[iq*4];
                float4 av4 = *(const float4*)&a3[iq*4];
                p += wv4.x*av4.x + wv4.y*av4.y + wv4.z*av4.z + wv4.w*av4.w;
            }
            p += __shfl_xor_sync(0xffffffffu, p, 1);
            p += __shfl_xor_sync(0xffffffffu, p, 2);
            if (q == 0) g_w1a3[e] = p;
            __syncthreads();
            if (tid == 0) {
                __threadfence();
                atomicExch(&g_flag, 1);
            }
        }

        // ---------------- GEMM path ----------------
        const int bmi = blockIdx.x & 63;
        const int bni = blockIdx.x >> 6;
        const int bm = bmi * 32;
        const int bn = bni * 64;
        const int tx = tid & 15;
        const int ty = tid >> 4;
        const int ar = tid >> 3;
        const int ac = (tid & 7) * 2;
        const int br = tid >> 4;
        const int bc = (tid & 15) * 4;

        unsigned long long acc00 = 0, acc01 = 0, acc10 = 0, acc11 = 0;
        for (int k0 = 0; k0 < FF; k0 += 16) {
            float2 xa = *(const float2*)&X[(size_t)(bm + ar)*FF + k0 + ac];
            As[ac][ar] = xa.x; As[ac+1][ar] = xa.y;
            *(float4*)&Bs[br][bc] = *(const float4*)&Wm[(size_t)(k0 + br)*FF + bn + bc];
            __syncthreads();
            #pragma unroll
            for (int k = 0; k < 16; k++) {
                float a0 = As[k][ty*2+0];
                float a1 = As[k][ty*2+1];
                unsigned long long a0d = pack2(a0, a0);
                unsigned long long a1d = pack2(a1, a1);
                ulonglong2 bq = *(const ulonglong2*)&Bs[k][tx*4];
                acc00 = ffma2(a0d, bq.x, acc00);
                acc01 = ffma2(a0d, bq.y, acc01);
                acc10 = ffma2(a1d, bq.x, acc10);
                acc11 = ffma2(a1d, bq.y, acc11);
            }
            __syncthreads();
        }
        float c00, c01, c02, c03, c10, c11, c12, c13;
        unpack2(acc00, c00, c01); unpack2(acc01, c02, c03);
        unpack2(acc10, c10, c11); unpack2(acc11, c12, c13);
        *(float4*)&g_h[(size_t)(bm + ty*2 + 0)*FF + bn + tx*4] = make_float4(c00, c01, c02, c03);
        *(float4*)&g_h[(size_t)(bm + ty*2 + 1)*FF + bn + tx*4] = make_float4(c10, c11, c12, c13);

        // epilogue: partial s_i/s_j over this n-tile
        const float4 a1v = *(const float4*)&a[bn + tx*4];
        const float4 a2v = *(const float4*)&a[FF + bn + tx*4];
        float pi0 = c00*a1v.x + c01*a1v.y + c02*a1v.z + c03*a1v.w;
        float pi1 = c10*a1v.x + c11*a1v.y + c12*a1v.z + c13*a1v.w;
        float pj0 = c00*a2v.x + c01*a2v.y + c02*a2v.z + c03*a2v.w;
        float pj1 = c10*a2v.x + c11*a2v.y + c12*a2v.z + c13*a2v.w;
        #pragma unroll
        for (int o = 8; o > 0; o >>= 1) {
            pi0 += __shfl_xor_sync(0xffffffffu, pi0, o);
            pi1 += __shfl_xor_sync(0xffffffffu, pi1, o);
            pj0 += __shfl_xor_sync(0xffffffffu, pj0, o);
            pj1 += __shfl_xor_sync(0xffffffffu, pj1, o);
        }
        if (tx == 0) {
            g_sip[bni*(BB*NN) + bm + ty*2 + 0] = pi0;
            g_sip[bni*(BB*NN) + bm + ty*2 + 1] = pi1;
            g_sjp[bni*(BB*NN) + bm + ty*2 + 0] = pj0;
            g_sjp[bni*(BB*NN) + bm + ty*2 + 1] = pj1;
        }
    } else {
        // ---------------- SCORE path (268 MB edge stream) ----------------
        const int bi = blockIdx.x - GEMM_CTAS;          // b*NN + i

        // wait for w1a3 (bid 0 is wave-1 resident -> guaranteed progress)
        if (tid < 32) {
            while (atomicAdd(&g_flag, 0) == 0) __nanosleep(100);
        }
        __syncthreads();
        if (tid < EE) s_w[tid] = g_w1a3[tid];
        __syncthreads();

        const int w = tid >> 5;
        const int lane = tid & 31;
        const int g = lane >> 4;
        const int l = lane & 15;
        const float4 wv = *(const float4*)&s_w[l*4];
        const float4* erow = (const float4*)(edge + (size_t)bi * NN * EE);
        const int jw = w * 64;

        #pragma unroll
        for (int t = 0; t < 8; t += 2) {
            // 8 independent LDG.128 in flight
            float4 ev[8];
            #pragma unroll
            for (int tt = 0; tt < 2; tt++) {
                const int jb = jw + (t + tt)*8 + g;
                #pragma unroll
                for (int u = 0; u < 4; u++)
                    ev[tt*4 + u] = erow[(size_t)(jb + 2*u)*16 + l];
            }
            #pragma unroll
            for (int tt = 0; tt < 2; tt++) {
                const int jb = jw + (t + tt)*8 + g;
                #pragma unroll
                for (int u = 0; u < 4; u++) {
                    float4 e4 = ev[tt*4 + u];
                    float p = e4.x*wv.x + e4.y*wv.y + e4.z*wv.z + e4.w*wv.w;
                    p += __shfl_xor_sync(0xffffffffu, p, 8);
                    p += __shfl_xor_sync(0xffffffffu, p, 4);
                    p += __shfl_xor_sync(0xffffffffu, p, 2);
                    p += __shfl_xor_sync(0xffffffffu, p, 1);
                    if (l == 0) s_sc[jb + 2*u] = p;
                }
            }
        }
        __syncthreads();
        *(float2*)&g_sc[(size_t)bi*NN + tid*2] = *(const float2*)&s_sc[tid*2];
    }
}

// ================= Kernel 2: softmax + attn@h + elu; TILE_I=8, 2 f/thread ======
// grid = 256 (b x 64 tiles), block 512 = 4 j-quarters x 128 f-lanes.
__global__ __launch_bounds__(512) void softmax_av_kernel(const float* __restrict__ adj,
                                                         float* __restrict__ out) {
    __shared__ __align__(16) float2 sh_ap[TILE_I/2][NN];  // packed (2r,2r+1) attn, 16KB
    __shared__ float redm[TILE_I][16];
    __shared__ float reds[TILE_I][16];
    __shared__ float s_si[TILE_I];

    const int tid  = threadIdx.x;
    const int b    = blockIdx.x >> 6;
    const int i0   = (blockIdx.x & 63) * TILE_I;
    const int lane = tid & 31;
    const int wid  = tid >> 5;

    if (tid < TILE_I) {
        float s = 0.f;
        #pragma unroll
        for (int t = 0; t < 4; t++) s += g_sip[t*(BB*NN) + b*NN + i0 + tid];
        s_si[tid] = s;
    }
    float sj = 0.f;
    #pragma unroll
    for (int t = 0; t < 4; t++) sj += g_sjp[t*(BB*NN) + b*NN + tid];
    __syncthreads();

    // ---- masked lrelu scores for 8 rows, column j = tid ----
    float v[TILE_I];
    const float* scb  = g_sc + (size_t)(b*NN + i0)*NN;
    const float* adjb = adj  + (size_t)(b*NN + i0)*NN;
    #pragma unroll
    for (int r = 0; r < TILE_I; r++) {
        float e = s_si[r] + sj + scb[(size_t)r*NN + tid];
        e = (e >= 0.f) ? e : LRELU_ALPHA * e;
        v[r] = (adjb[(size_t)r*NN + tid] > 0.f) ? e : NEG_INF_V;
    }
    #pragma unroll
    for (int r = 0; r < TILE_I; r++) {
        float m = v[r];
        #pragma unroll
        for (int o = 16; o > 0; o >>= 1)
            m = fmaxf(m, __shfl_xor_sync(0xffffffffu, m, o));
        if (lane == 0) redm[r][wid] = m;
    }
    __syncthreads();
    #pragma unroll
    for (int r = 0; r < TILE_I; r++) {
        float bm = redm[r][0];
        #pragma unroll
        for (int wq = 1; wq < 16; wq++) bm = fmaxf(bm, redm[r][wq]);
        v[r] = __expf(v[r] - bm);
        float s = v[r];
        #pragma unroll
        for (int o = 16; o > 0; o >>= 1)
            s += __shfl_xor_sync(0xffffffffu, s, o);
        if (lane == 0) reds[r][wid] = s;
    }
    __syncthreads();
    #pragma unroll
    for (int rp = 0; rp < TILE_I/2; rp++) {
        float s0 = 0.f, s1 = 0.f;
        #pragma unroll
        for (int wq = 0; wq < 16; wq++) { s0 += reds[2*rp][wq]; s1 += reds[2*rp+1][wq]; }
        sh_ap[rp][tid] = make_float2(v[2*rp] / s0, v[2*rp+1] / s1);
    }
    __syncthreads();

    // ---- attn @ h: 4 j-quarters, 2 f per thread (fl, fl+128); row-pair FFMA2 ----
    const int jq = tid >> 7;             // 0..3
    const int fl = tid & 127;
    unsigned long long acc0[TILE_I/2] = {};   // f = fl
    unsigned long long acc1[TILE_I/2] = {};   // f = fl + 128
    const float* hb = g_h + (size_t)b*NN*FF;

    for (int jt = jq*128; jt < jq*128 + 128; jt += 4) {
        unsigned long long hd0[4], hd1[4];
        #pragma unroll
        for (int u = 0; u < 4; u++) {
            float h0 = hb[(size_t)(jt + u)*FF + fl];
            float h1 = hb[(size_t)(jt + u)*FF + fl + 128];
            hd0[u] = pack2(h0, h0);
            hd1[u] = pack2(h1, h1);
        }
        #pragma unroll
        for (int rp = 0; rp < TILE_I/2; rp++) {
            ulonglong2 q0 = *(const ulonglong2*)&sh_ap[rp][jt + 0];
            ulonglong2 q1 = *(const ulonglong2*)&sh_ap[rp][jt + 2];
            acc0[rp] = ffma2(q0.x, hd0[0], acc0[rp]);
            acc0[rp] = ffma2(q0.y, hd0[1], acc0[rp]);
            acc0[rp] = ffma2(q1.x, hd0[2], acc0[rp]);
            acc0[rp] = ffma2(q1.y, hd0[3], acc0[rp]);
            acc1[rp] = ffma2(q0.x, hd1[0], acc1[rp]);
            acc1[rp] = ffma2(q0.y, hd1[1], acc1[rp]);
            acc1[rp] = ffma2(q1.x, hd1[2], acc1[rp]);
            acc1[rp] = ffma2(q1.y, hd1[3], acc1[rp]);
        }
    }

    // ---- combine 4 quarters (staged through 16KB sh_ap overlay), ELU, store ----
    __syncthreads();
    float2* buf = (float2*)&sh_ap[0][0];   // 2048 float2 = 16KB
    // layout: [src(0..1)][rp(0..3)][fsel(0..1)][fl(0..127)]
    if (jq >= 2) {
        #pragma unroll
        for (int rp = 0; rp < TILE_I/2; rp++) {
            float lo, hi;
            unpack2(acc0[rp], lo, hi);
            buf[(((jq-2)*4 + rp)*2 + 0)*128 + fl] = make_float2(lo, hi);
            unpack2(acc1[rp], lo, hi);
            buf[(((jq-2)*4 + rp)*2 + 1)*128 + fl] = make_float2(lo, hi);
        }
    }
    __syncthreads();
    if (jq < 2) {   // q0 += q2's partial; q1 += q3's partial
        #pragma unroll
        for (int rp = 0; rp < TILE_I/2; rp++) {
            float2 p0 = buf[((jq*4 + rp)*2 + 0)*128 + fl];
            float2 p1 = buf[((jq*4 + rp)*2 + 1)*128 + fl];
            float lo, hi;
            unpack2(acc0[rp], lo, hi);
            acc0[rp] = pack2(lo + p0.x, hi + p0.y);
            unpack2(acc1[rp], lo, hi);
            acc1[rp] = pack2(lo + p1.x, hi + p1.y);
        }
    }
    __syncthreads();
    if (jq == 1) {
        #pragma unroll
        for (int rp = 0; rp < TILE_I/2; rp++) {
            float lo, hi;
            unpack2(acc0[rp], lo, hi);
            buf[((rp)*2 + 0)*128 + fl] = make_float2(lo, hi);
            unpack2(acc1[rp], lo, hi);
            buf[((rp)*2 + 1)*128 + fl] = make_float2(lo, hi);
        }
    }
    __syncthreads();
    if (jq == 0) {
        #pragma unroll
        for (int rp = 0; rp < TILE_I/2; rp++) {
            float2 p0 = buf[((rp)*2 + 0)*128 + fl];
            float2 p1 = buf[((rp)*2 + 1)*128 + fl];
            float lo, hi;
            unpack2(acc0[rp], lo, hi);
            float v00 = lo + p0.x, v01 = hi + p0.y;
            unpack2(acc1[rp], lo, hi);
            float v10 = lo + p1.x, v11 = hi + p1.y;
            out[(size_t)(b*NN + i0 + 2*rp + 0)*FF + fl]       = (v00 > 0.f) ? v00 : expm1f(v00);
            out[(size_t)(b*NN + i0 + 2*rp + 1)*FF + fl]       = (v01 > 0.f) ? v01 : expm1f(v01);
            out[(size_t)(b*NN + i0 + 2*rp + 0)*FF + fl + 128] = (v10 > 0.f) ? v10 : expm1f(v10);
            out[(size_t)(b*NN + i0 + 2*rp + 1)*FF + fl + 128] = (v11 > 0.f) ? v11 : expm1f(v11);
        }
    }
}

// ================= launcher =================
extern "C" void kernel_launch(void* const* d_in, const int* in_sizes, int n_in,
                              void* d_out, int out_size) {
    const float* x    = (const float*)d_in[0];  // [4,512,256]
    const float* edge = (const float*)d_in[1];  // [4,512,512,64]
    const float* adj  = (const float*)d_in[2];  // [4,512,512]
    const float* W    = (const float*)d_in[3];  // [256,256]
    const float* W1   = (const float*)d_in[4];  // [64,256]
    const float* a    = (const float*)d_in[5];  // [768,1]
    float* out = (float*)d_out;                 // [4,512,256]

    mega_kernel<<<GEMM_CTAS + BB*NN, 256>>>(x, W, edge, W1, a);
    softmax_av_kernel<<<BB*NN/TILE_I, 512>>>(adj, out);
}

// round 8
// speedup vs baseline: 1.8763x; 1.4587x over previous
#include <cuda_runtime.h>
#include <math.h>

#define BB 4
#define NN 512
#define FF 256
#define EE 64
#define TILE_I 8
#define LRELU_ALPHA 0.2f
#define NEG_INF_V -1e30f

#define GEMM_CTAS 256   // 64 m-tiles x 4 n-tiles

// scratch (no allocations allowed)
__device__ float g_h[BB*NN*FF];        // 2 MB
__device__ float g_sip[4*BB*NN];       // per-n-tile partial s_i
__device__ float g_sjp[4*BB*NN];       // per-n-tile partial s_j
__device__ float g_w1a3[EE];
__device__ float g_sc[BB*NN*NN];       // 4 MB raw edge scores

// ---- f32x2 packed helpers (Blackwell FFMA2) ----
__device__ __forceinline__ unsigned long long ffma2(unsigned long long a,
                                                    unsigned long long b,
                                                    unsigned long long c) {
    unsigned long long d;
    asm("fma.rn.f32x2 %0, %1, %2, %3;" : "=l"(d) : "l"(a), "l"(b), "l"(c));
    return d;
}
__device__ __forceinline__ unsigned long long pack2(float lo, float hi) {
    unsigned long long d;
    asm("mov.b64 %0, {%1, %2};" : "=l"(d) : "f"(lo), "f"(hi));
    return d;
}
__device__ __forceinline__ void unpack2(unsigned long long v, float& lo, float& hi) {
    asm("mov.b64 {%0, %1}, %2;" : "=f"(lo), "=f"(hi) : "l"(v));
}

// ================= Kernel 0: w1a3[e] = W1[e,:]·a3 =================
__global__ void w1a3_kernel(const float* __restrict__ W1, const float* __restrict__ a) {
    const int wid  = threadIdx.x >> 5;
    const int lane = threadIdx.x & 31;
    const int e = blockIdx.x * 32 + wid;
    if (e >= EE) return;
    float p = 0.f;
    #pragma unroll
    for (int c = lane; c < FF; c += 32)
        p += W1[(size_t)e*FF + c] * __ldg(&a[2*FF + c]);
    #pragma unroll
    for (int o = 16; o > 0; o >>= 1)
        p += __shfl_xor_sync(0xffffffffu, p, o);
    if (lane == 0) g_w1a3[e] = p;
}

// ================= Kernel 1: MEGA (R5 verbatim — measured at DRAM roofline) ==========
__global__ __launch_bounds__(256) void mega_kernel(const float* __restrict__ X,
                                                   const float* __restrict__ Wm,
                                                   const float* __restrict__ edge,
                                                   const float* __restrict__ a) {
    __shared__ __align__(16) float As[16][33];   // gemm path
    __shared__ __align__(16) float Bs[16][68];
    __shared__ float s_w[EE];                    // score path
    __shared__ float s_sc[NN];

    const int tid = threadIdx.x;

    if (blockIdx.x < GEMM_CTAS) {
        // ---------------- GEMM path ----------------
        const int bmi = blockIdx.x & 63;
        const int bni = blockIdx.x >> 6;
        const int bm = bmi * 32;
        const int bn = bni * 64;
        const int tx = tid & 15;
        const int ty = tid >> 4;
        const int ar = tid >> 3;
        const int ac = (tid & 7) * 2;
        const int br = tid >> 4;
        const int bc = (tid & 15) * 4;

        unsigned long long acc00 = 0, acc01 = 0, acc10 = 0, acc11 = 0;
        for (int k0 = 0; k0 < FF; k0 += 16) {
            float2 xa = *(const float2*)&X[(size_t)(bm + ar)*FF + k0 + ac];
            As[ac][ar] = xa.x; As[ac+1][ar] = xa.y;
            *(float4*)&Bs[br][bc] = *(const float4*)&Wm[(size_t)(k0 + br)*FF + bn + bc];
            __syncthreads();
            #pragma unroll
            for (int k = 0; k < 16; k++) {
                float a0 = As[k][ty*2+0];
                float a1 = As[k][ty*2+1];
                unsigned long long a0d = pack2(a0, a0);
                unsigned long long a1d = pack2(a1, a1);
                ulonglong2 bq = *(const ulonglong2*)&Bs[k][tx*4];
                acc00 = ffma2(a0d, bq.x, acc00);
                acc01 = ffma2(a0d, bq.y, acc01);
                acc10 = ffma2(a1d, bq.x, acc10);
                acc11 = ffma2(a1d, bq.y, acc11);
            }
            __syncthreads();
        }
        float c00, c01, c02, c03, c10, c11, c12, c13;
        unpack2(acc00, c00, c01); unpack2(acc01, c02, c03);
        unpack2(acc10, c10, c11); unpack2(acc11, c12, c13);
        *(float4*)&g_h[(size_t)(bm + ty*2 + 0)*FF + bn + tx*4] = make_float4(c00, c01, c02, c03);
        *(float4*)&g_h[(size_t)(bm + ty*2 + 1)*FF + bn + tx*4] = make_float4(c10, c11, c12, c13);

        // epilogue: partial s_i/s_j over this n-tile
        const float4 a1v = *(const float4*)&a[bn + tx*4];
        const float4 a2v = *(const float4*)&a[FF + bn + tx*4];
        float pi0 = c00*a1v.x + c01*a1v.y + c02*a1v.z + c03*a1v.w;
        float pi1 = c10*a1v.x + c11*a1v.y + c12*a1v.z + c13*a1v.w;
        float pj0 = c00*a2v.x + c01*a2v.y + c02*a2v.z + c03*a2v.w;
        float pj1 = c10*a2v.x + c11*a2v.y + c12*a2v.z + c13*a2v.w;
        #pragma unroll
        for (int o = 8; o > 0; o >>= 1) {
            pi0 += __shfl_xor_sync(0xffffffffu, pi0, o);
            pi1 += __shfl_xor_sync(0xffffffffu, pi1, o);
            pj0 += __shfl_xor_sync(0xffffffffu, pj0, o);
            pj1 += __shfl_xor_sync(0xffffffffu, pj1, o);
        }
        if (tx == 0) {
            g_sip[bni*(BB*NN) + bm + ty*2 + 0] = pi0;
            g_sip[bni*(BB*NN) + bm + ty*2 + 1] = pi1;
            g_sjp[bni*(BB*NN) + bm + ty*2 + 0] = pj0;
            g_sjp[bni*(BB*NN) + bm + ty*2 + 1] = pj1;
        }
    } else {
        // ---------------- SCORE path (268 MB edge stream) ----------------
        const int bi = blockIdx.x - GEMM_CTAS;          // b*NN + i
        if (tid < EE) s_w[tid] = g_w1a3[tid];
        __syncthreads();

        const int w = tid >> 5;
        const int lane = tid & 31;
        const int g = lane >> 4;
        const int l = lane & 15;
        const float4 wv = *(const float4*)&s_w[l*4];
        const float4* erow = (const float4*)(edge + (size_t)bi * NN * EE);
        const int jw = w * 64;

        #pragma unroll
        for (int t = 0; t < 8; t += 2) {
            // 8 independent LDG.128 in flight
            float4 ev[8];
            #pragma unroll
            for (int tt = 0; tt < 2; tt++) {
                const int jb = jw + (t + tt)*8 + g;
                #pragma unroll
                for (int u = 0; u < 4; u++)
                    ev[tt*4 + u] = erow[(size_t)(jb + 2*u)*16 + l];
            }
            #pragma unroll
            for (int tt = 0; tt < 2; tt++) {
                const int jb = jw + (t + tt)*8 + g;
                #pragma unroll
                for (int u = 0; u < 4; u++) {
                    float4 e4 = ev[tt*4 + u];
                    float p = e4.x*wv.x + e4.y*wv.y + e4.z*wv.z + e4.w*wv.w;
                    p += __shfl_xor_sync(0xffffffffu, p, 8);
                    p += __shfl_xor_sync(0xffffffffu, p, 4);
                    p += __shfl_xor_sync(0xffffffffu, p, 2);
                    p += __shfl_xor_sync(0xffffffffu, p, 1);
                    if (l == 0) s_sc[jb + 2*u] = p;
                }
            }
        }
        __syncthreads();
        *(float2*)&g_sc[(size_t)bi*NN + tid*2] = *(const float2*)&s_sc[tid*2];
    }
}

// ================= Kernel 2: softmax(row-per-warp-pair, unnormalized) + attn@h + elu ===
// grid = 256 (b x 64 tiles), block 512. Normalization folded into epilogue.
__global__ __launch_bounds__(512) void softmax_av_kernel(const float* __restrict__ adj,
                                                         float* __restrict__ out) {
    __shared__ __align__(16) float2 sh_ap[TILE_I/2][NN];  // packed (2r,2r+1) raw exp, 16KB
    __shared__ float sh_sj[NN];
    __shared__ float redm[TILE_I][2];
    __shared__ float reds[TILE_I][2];
    __shared__ float s_si[TILE_I];

    const int tid  = threadIdx.x;
    const int b    = blockIdx.x >> 6;
    const int i0   = (blockIdx.x & 63) * TILE_I;
    const int lane = tid & 31;
    const int w    = tid >> 5;

    // pass 0: sj per column, si per row
    {
        float sjv = 0.f;
        #pragma unroll
        for (int t = 0; t < 4; t++) sjv += g_sjp[t*(BB*NN) + b*NN + tid];
        sh_sj[tid] = sjv;
        if (tid < TILE_I) {
            float s = 0.f;
            #pragma unroll
            for (int t = 0; t < 4; t++) s += g_sip[t*(BB*NN) + b*NN + i0 + tid];
            s_si[tid] = s;
        }
    }
    __syncthreads();

    // ---- softmax phase: warp pair (r = w>>1, half hh = w&1), 8 j per thread ----
    const int r  = w >> 1;
    const int hh = w & 1;
    const int j0 = hh*256 + lane;
    const float si = s_si[r];
    const float* scr = g_sc + (size_t)(b*NN + i0 + r)*NN;
    const float* adr = adj  + (size_t)(b*NN + i0 + r)*NN;

    float e8[8];
    float mx = NEG_INF_V;
    #pragma unroll
    for (int k = 0; k < 8; k++) {
        const int j = j0 + k*32;
        float e = si + sh_sj[j] + scr[j];
        e = (e >= 0.f) ? e : LRELU_ALPHA * e;
        e = (adr[j] > 0.f) ? e : NEG_INF_V;
        e8[k] = e;
        mx = fmaxf(mx, e);
    }
    #pragma unroll
    for (int o = 16; o > 0; o >>= 1)
        mx = fmaxf(mx, __shfl_xor_sync(0xffffffffu, mx, o));
    if (lane == 0) redm[r][hh] = mx;
    __syncthreads();
    const float bm = fmaxf(redm[r][0], redm[r][1]);

    float sum = 0.f;
    #pragma unroll
    for (int k = 0; k < 8; k++) {
        e8[k] = __expf(e8[k] - bm);
        sum += e8[k];
    }
    #pragma unroll
    for (int o = 16; o > 0; o >>= 1)
        sum += __shfl_xor_sync(0xffffffffu, sum, o);
    if (lane == 0) reds[r][hh] = sum;

    // store raw exp packed: sh_ap[r>>1][j].{x|y} per (r&1)
    {
        float* base = (float*)&sh_ap[r >> 1][0];
        const int comp = r & 1;
        #pragma unroll
        for (int k = 0; k < 8; k++)
            base[(j0 + k*32)*2 + comp] = e8[k];
    }
    __syncthreads();

    // ---- attn @ h: 4 j-quarters, 2 f per thread (fl, fl+128); row-pair FFMA2 ----
    const int jq = tid >> 7;             // 0..3
    const int fl = tid & 127;
    unsigned long long acc0[TILE_I/2] = {};   // f = fl
    unsigned long long acc1[TILE_I/2] = {};   // f = fl + 128
    const float* hb = g_h + (size_t)b*NN*FF;

    for (int jt = jq*128; jt < jq*128 + 128; jt += 4) {
        unsigned long long hd0[4], hd1[4];
        #pragma unroll
        for (int u = 0; u < 4; u++) {
            float h0 = hb[(size_t)(jt + u)*FF + fl];
            float h1 = hb[(size_t)(jt + u)*FF + fl + 128];
            hd0[u] = pack2(h0, h0);
            hd1[u] = pack2(h1, h1);
        }
        #pragma unroll
        for (int rp = 0; rp < TILE_I/2; rp++) {
            ulonglong2 q0 = *(const ulonglong2*)&sh_ap[rp][jt + 0];
            ulonglong2 q1 = *(const ulonglong2*)&sh_ap[rp][jt + 2];
            acc0[rp] = ffma2(q0.x, hd0[0], acc0[rp]);
            acc0[rp] = ffma2(q0.y, hd0[1], acc0[rp]);
            acc0[rp] = ffma2(q1.x, hd0[2], acc0[rp]);
            acc0[rp] = ffma2(q1.y, hd0[3], acc0[rp]);
            acc1[rp] = ffma2(q0.x, hd1[0], acc1[rp]);
            acc1[rp] = ffma2(q0.y, hd1[1], acc1[rp]);
            acc1[rp] = ffma2(q1.x, hd1[2], acc1[rp]);
            acc1[rp] = ffma2(q1.y, hd1[3], acc1[rp]);
        }
    }

    // ---- combine 4 quarters (staged through 16KB sh_ap overlay), normalize, ELU, store ----
    __syncthreads();
    float2* buf = (float2*)&sh_ap[0][0];   // 2048 float2 = 16KB
    if (jq >= 2) {
        #pragma unroll
        for (int rp = 0; rp < TILE_I/2; rp++) {
            float lo, hi;
            unpack2(acc0[rp], lo, hi);
            buf[(((jq-2)*4 + rp)*2 + 0)*128 + fl] = make_float2(lo, hi);
            unpack2(acc1[rp], lo, hi);
            buf[(((jq-2)*4 + rp)*2 + 1)*128 + fl] = make_float2(lo, hi);
        }
    }
    __syncthreads();
    if (jq < 2) {   // q0 += q2's partial; q1 += q3's partial
        #pragma unroll
        for (int rp = 0; rp < TILE_I/2; rp++) {
            float2 p0 = buf[((jq*4 + rp)*2 + 0)*128 + fl];
            float2 p1 = buf[((jq*4 + rp)*2 + 1)*128 + fl];
            float lo, hi;
            unpack2(acc0[rp], lo, hi);
            acc0[rp] = pack2(lo + p0.x, hi + p0.y);
            unpack2(acc1[rp], lo, hi);
            acc1[rp] = pack2(lo + p1.x, hi + p1.y);
        }
    }
    __syncthreads();
    if (jq == 1) {
        #pragma unroll
        for (int rp = 0; rp < TILE_I/2; rp++) {
            float lo, hi;
            unpack2(acc0[rp], lo, hi);
            buf[((rp)*2 + 0)*128 + fl] = make_float2(lo, hi);
            unpack2(acc1[rp], lo, hi);
            buf[((rp)*2 + 1)*128 + fl] = make_float2(lo, hi);
        }
    }
    __syncthreads();
    if (jq == 0) {
        #pragma unroll
        for (int rp = 0; rp < TILE_I/2; rp++) {
            const float inv0 = 1.f / (reds[2*rp][0]   + reds[2*rp][1]);
            const float inv1 = 1.f / (reds[2*rp+1][0] + reds[2*rp+1][1]);
            float2 p0 = buf[((rp)*2 + 0)*128 + fl];
            float2 p1 = buf[((rp)*2 + 1)*128 + fl];
            float lo, hi;
            unpack2(acc0[rp], lo, hi);
            float v00 = (lo + p0.x) * inv0, v01 = (hi + p0.y) * inv1;
            unpack2(acc1[rp], lo, hi);
            float v10 = (lo + p1.x) * inv0, v11 = (hi + p1.y) * inv1;
            out[(size_t)(b*NN + i0 + 2*rp + 0)*FF + fl]       = (v00 > 0.f) ? v00 : expm1f(v00);
            out[(size_t)(b*NN + i0 + 2*rp + 1)*FF + fl]       = (v01 > 0.f) ? v01 : expm1f(v01);
            out[(size_t)(b*NN + i0 + 2*rp + 0)*FF + fl + 128] = (v10 > 0.f) ? v10 : expm1f(v10);
            out[(size_t)(b*NN + i0 + 2*rp + 1)*FF + fl + 128] = (v11 > 0.f) ? v11 : expm1f(v11);
        }
    }
}

// ================= launcher =================
extern "C" void kernel_launch(void* const* d_in, const int* in_sizes, int n_in,
                              void* d_out, int out_size) {
    const float* x    = (const float*)d_in[0];  // [4,512,256]
    const float* edge = (const float*)d_in[1];  // [4,512,512,64]
    const float* adj  = (const float*)d_in[2];  // [4,512,512]
    const float* W    = (const float*)d_in[3];  // [256,256]
    const float* W1   = (const float*)d_in[4];  // [64,256]
    const float* a    = (const float*)d_in[5];  // [768,1]
    float* out = (float*)d_out;                 // [4,512,256]

    w1a3_kernel<<<2, 1024>>>(W1, a);
    mega_kernel<<<GEMM_CTAS + BB*NN, 256>>>(x, W, edge, a);
    softmax_av_kernel<<<BB*NN/TILE_I, 512>>>(adj, out);
}